// round 16
// baseline (speedup 1.0000x reference)
#include <cuda_runtime.h>
#include <math.h>

// ---------------------------------------------------------------------------
// Shapes
// ---------------------------------------------------------------------------
#define D        32
#define NU_C     100001
#define NI_C     50001
#define NTOT_C   (NU_C + NI_C)          // 150002
#define NOFF     (NTOT_C + 1)
#define BMAX     4096
#define SCAN_B   256
#define NBLK_SCAN ((NOFF + SCAN_B - 1) / SCAN_B)
#define SUMS_STRIDE 640
#define CSR_CAP  6400000

// ---------------------------------------------------------------------------
// Device scratch
// ---------------------------------------------------------------------------
__device__ float g_emb[NTOT_C * D];
__device__ float g_pc0[NTOT_C * D];     // comb0 layer1
__device__ float g_pc1[NTOT_C * D];     // comb1 layer1
__device__ float g_ae0[NTOT_C * D];     // ae0
__device__ float g_ae1[NTOT_C * D];     // ae1
__device__ float g_a0 [NTOT_C * D];     // aux0 layer1; later de0 layer1
__device__ float g_a1 [NTOT_C * D];     // aux1 layer1; later de1 layer1
__device__ int    g_degi [3 * NTOT_C];  // aux0, aux1, tgt
__device__ float  g_dnv  [5 * NTOT_C];  // SoA: c0, c1, a0, a1, t
__device__ float2 g_dnv2 [3 * NTOT_C];  // pairs: (c0,a0), (c1,a1), (c0,c1)
__device__ int   g_off  [3 * NOFF];
__device__ int   g_curs [3 * NOFF];
__device__ int   g_bsums[3 * SUMS_STRIDE];
__device__ int   g_csr  [CSR_CAP];      // neighbor indices only
// score slots: CP=0 CN=1 AP=2 AN=3 DP=4 DN=5; offset = (slot*2 + idx)*BMAX + b
__device__ float g_sc  [12 * BMAX];
__device__ float g_scal[4];

// ---------------------------------------------------------------------------
// Helpers
// ---------------------------------------------------------------------------
__device__ __forceinline__ float logsig(float x) {
    return (x >= 0.f) ? -log1pf(expf(-x)) : (x - log1pf(expf(x)));
}

__device__ __forceinline__ void fma4(float4& a, float w, float4 v) {
    a.x = fmaf(w, v.x, a.x);
    a.y = fmaf(w, v.y, a.y);
    a.z = fmaf(w, v.z, a.z);
    a.w = fmaf(w, v.w, a.w);
}

// warp-per-row weighted gather (scoring kernels; R10-proven shape)
__device__ __forceinline__ float gather_w(const int* __restrict__ csr,
                                          int k, int end,
                                          const float* __restrict__ dnv,
                                          const float* __restrict__ src,
                                          int lane) {
    float acc = 0.f;
    for (; k + 8 <= end; k += 8) {
        int e[8]; float w[8];
        #pragma unroll
        for (int j = 0; j < 8; j++) e[j] = __ldg(&csr[k + j]);
        #pragma unroll
        for (int j = 0; j < 8; j++) w[j] = __ldg(&dnv[e[j]]);
        #pragma unroll
        for (int j = 0; j < 8; j++)
            acc = fmaf(w[j], __ldg(&src[(size_t)e[j] * D + lane]), acc);
    }
    for (; k < end; k++) {
        int e = __ldg(&csr[k]);
        acc = fmaf(__ldg(&dnv[e]), __ldg(&src[(size_t)e * D + lane]), acc);
    }
    return acc;
}

// ---------------------------------------------------------------------------
// Graph build (identical to R10)
// ---------------------------------------------------------------------------
__global__ void k_deg3(const int2* __restrict__ aux, const int2* __restrict__ tgt,
                       int Ea, int Et, int nu) {
    int t = blockIdx.x * blockDim.x + threadIdx.x;
    int2 ed; int slot;
    if (t < 2 * Ea)            { ed = aux[t];          slot = (t < Ea) ? 0 : 1; }
    else if (t < 2 * Ea + Et)  { ed = tgt[t - 2 * Ea]; slot = 2; }
    else return;
    int* deg = g_degi + slot * NTOT_C;
    atomicAdd(&deg[ed.x], 1);
    atomicAdd(&deg[nu + ed.y], 1);
}

__global__ void k_dinv5() {
    int i = blockIdx.x * blockDim.x + threadIdx.x;
    if (i >= NTOT_C) return;
    int d0 = g_degi[0 * NTOT_C + i];
    int d1 = g_degi[1 * NTOT_C + i];
    int dt = g_degi[2 * NTOT_C + i];
    int dd[5] = {d0 + dt, d1 + dt, d0, d1, dt};
    float w[5];
    #pragma unroll
    for (int s = 0; s < 5; s++) {
        w[s] = (dd[s] > 0) ? rsqrtf((float)dd[s]) : 0.f;
        g_dnv[s * NTOT_C + i] = w[s];
    }
    g_dnv2[0 * NTOT_C + i] = make_float2(w[0], w[2]);  // (c0, a0)
    g_dnv2[1 * NTOT_C + i] = make_float2(w[1], w[3]);  // (c1, a1)
    g_dnv2[2 * NTOT_C + i] = make_float2(w[0], w[1]);  // (c0, c1)
}

__global__ void k_scanA() {
    int g = blockIdx.y;
    const int* deg = g_degi + g * NTOT_C;
    int* out  = g_off   + g * NOFF;
    int* sums = g_bsums + g * SUMS_STRIDE;
    int idx = blockIdx.x * SCAN_B + threadIdx.x;
    int val = (idx < NTOT_C) ? deg[idx] : 0;
    int lane = threadIdx.x & 31, wid = threadIdx.x >> 5;
    int x = val;
    #pragma unroll
    for (int o = 1; o < 32; o <<= 1) {
        int y = __shfl_up_sync(0xffffffffu, x, o);
        if (lane >= o) x += y;
    }
    __shared__ int ws[8], wbase[8];
    if (lane == 31) ws[wid] = x;
    __syncthreads();
    if (threadIdx.x == 0) {
        int s = 0;
        for (int i = 0; i < 8; i++) { wbase[i] = s; s += ws[i]; }
    }
    __syncthreads();
    int incl = x + wbase[wid];
    if (idx < NOFF) out[idx] = incl - val;
    if (threadIdx.x == SCAN_B - 1) sums[blockIdx.x] = incl;
}

__global__ void k_scanB(int nb) {
    int g = blockIdx.x;
    int* sums = g_bsums + g * SUMS_STRIDE;
    __shared__ int sh[SUMS_STRIDE];
    int tid = threadIdx.x;
    int orig = 0;
    if (tid < nb) { orig = sums[tid]; sh[tid] = orig; }
    __syncthreads();
    for (int o = 1; o < nb; o <<= 1) {
        int v = 0;
        if (tid < nb && tid >= o) v = sh[tid - o];
        __syncthreads();
        if (tid < nb && tid >= o) sh[tid] += v;
        __syncthreads();
    }
    if (tid < nb) sums[tid] = sh[tid] - orig;
}

__global__ void k_scanC() {
    int g = blockIdx.y;
    int idx = blockIdx.x * SCAN_B + threadIdx.x;
    if (idx < NOFF)
        g_off[g * NOFF + idx] += g_bsums[g * SUMS_STRIDE + blockIdx.x];
}

__global__ void k_fill3(const int2* __restrict__ aux, const int2* __restrict__ tgt,
                        int Ea, int Et, int nu) {
    int t = blockIdx.x * blockDim.x + threadIdx.x;
    int2 ed; int slot; long long base;
    if (t < 2 * Ea) {
        ed = aux[t];
        slot = (t < Ea) ? 0 : 1;
        base = (t < Ea) ? 0 : 2LL * Ea;
    } else if (t < 2 * Ea + Et) {
        ed = tgt[t - 2 * Ea]; slot = 2; base = 4LL * Ea;
    } else return;
    int* curs = g_curs + slot * NOFF;
    int* csr  = g_csr + base;
    int u = ed.x, v = nu + ed.y;
    csr[atomicAdd(&curs[u], 1)] = v;
    csr[atomicAdd(&curs[v], 1)] = u;
}

// ---------------------------------------------------------------------------
// Propagation — EIGHT nodes per warp, 8 columns per lane (two float4)
// lanes [4q, 4q+4) -> node 8w+q; lane covers cols 8s..8s+7 (s = lane&3)
// ---------------------------------------------------------------------------
// paired float2 weights -> two outputs; optional accumulate
__global__ void __launch_bounds__(256)
k_dual_w8(const int* __restrict__ csr, const int* __restrict__ off,
          const float* __restrict__ src,
          const float2* __restrict__ w2,
          const float* __restrict__ wXs, const float* __restrict__ wYs,
          float* __restrict__ outX, float* __restrict__ outY, int ntot, int accum) {
    int w = (blockIdx.x * blockDim.x + threadIdx.x) >> 5;
    int lane = threadIdx.x & 31;
    int q   = lane >> 2;
    int sub = lane & 3;
    int u = 8 * w + q;
    int k = 0, end = 0;
    if (u < ntot) { k = off[u]; end = off[u + 1]; }
    float4 aX0 = make_float4(0.f, 0.f, 0.f, 0.f), aX1 = aX0;
    float4 aY0 = aX0, aY1 = aX0;
    for (; k < end; k += 4) {
        int e[4]; float2 ww[4];
        #pragma unroll
        for (int j = 0; j < 4; j++) {
            int kk = k + j;
            e[j] = __ldg(&csr[kk < end ? kk : k]);
        }
        #pragma unroll
        for (int j = 0; j < 4; j++)
            ww[j] = (k + j < end) ? __ldg(&w2[e[j]]) : make_float2(0.f, 0.f);
        #pragma unroll
        for (int j = 0; j < 4; j++) {
            const float4* rp = (const float4*)(src + (size_t)e[j] * D) + 2 * sub;
            float4 v0 = __ldg(rp);
            float4 v1 = __ldg(rp + 1);
            fma4(aX0, ww[j].x, v0); fma4(aX1, ww[j].x, v1);
            fma4(aY0, ww[j].y, v0); fma4(aY1, ww[j].y, v1);
        }
    }
    if (u >= ntot) return;
    size_t o = (size_t)u * D + 8 * sub;
    float sx = __ldg(&wXs[u]);
    float sy = __ldg(&wYs[u]);
    float4 rx0 = make_float4(sx * aX0.x, sx * aX0.y, sx * aX0.z, sx * aX0.w);
    float4 rx1 = make_float4(sx * aX1.x, sx * aX1.y, sx * aX1.z, sx * aX1.w);
    float4 ry0 = make_float4(sy * aY0.x, sy * aY0.y, sy * aY0.z, sy * aY0.w);
    float4 ry1 = make_float4(sy * aY1.x, sy * aY1.y, sy * aY1.z, sy * aY1.w);
    if (accum) {
        float4 p;
        p = *(const float4*)(outX + o);     rx0.x += p.x; rx0.y += p.y; rx0.z += p.z; rx0.w += p.w;
        p = *(const float4*)(outX + o + 4); rx1.x += p.x; rx1.y += p.y; rx1.z += p.z; rx1.w += p.w;
        p = *(const float4*)(outY + o);     ry0.x += p.x; ry0.y += p.y; ry0.z += p.z; ry0.w += p.w;
        p = *(const float4*)(outY + o + 4); ry1.x += p.x; ry1.y += p.y; ry1.z += p.z; ry1.w += p.w;
    }
    *(float4*)(outX + o)     = rx0;
    *(float4*)(outX + o + 4) = rx1;
    *(float4*)(outY + o)     = ry0;
    *(float4*)(outY + o + 4) = ry1;
}

// aux layer-2: out = (w[u]*gather + src + base)/3, octet nodes
__global__ void __launch_bounds__(256)
k_gcn_w8(const int* __restrict__ csr, const int* __restrict__ off,
         const float* __restrict__ w,
         const float* __restrict__ src, const float* __restrict__ base,
         float* __restrict__ out, int ntot) {
    int wp = (blockIdx.x * blockDim.x + threadIdx.x) >> 5;
    int lane = threadIdx.x & 31;
    int q   = lane >> 2;
    int sub = lane & 3;
    int u = 8 * wp + q;
    int k = 0, end = 0;
    if (u < ntot) { k = off[u]; end = off[u + 1]; }
    float4 a0 = make_float4(0.f, 0.f, 0.f, 0.f), a1 = a0;
    for (; k < end; k += 4) {
        int e[4]; float ww[4];
        #pragma unroll
        for (int j = 0; j < 4; j++) {
            int kk = k + j;
            e[j] = __ldg(&csr[kk < end ? kk : k]);
        }
        #pragma unroll
        for (int j = 0; j < 4; j++)
            ww[j] = (k + j < end) ? __ldg(&w[e[j]]) : 0.f;
        #pragma unroll
        for (int j = 0; j < 4; j++) {
            const float4* rp = (const float4*)(src + (size_t)e[j] * D) + 2 * sub;
            float4 v0 = __ldg(rp);
            float4 v1 = __ldg(rp + 1);
            fma4(a0, ww[j], v0);
            fma4(a1, ww[j], v1);
        }
    }
    if (u >= ntot) return;
    size_t o = (size_t)u * D + 8 * sub;
    float wu = __ldg(&w[u]);
    float4 s0 = *(const float4*)(src + o);
    float4 s1 = *(const float4*)(src + o + 4);
    float4 b0 = *(const float4*)(base + o);
    float4 b1 = *(const float4*)(base + o + 4);
    float4 r0, r1;
    r0.x = (wu * a0.x + s0.x + b0.x) * (1.f / 3.f);
    r0.y = (wu * a0.y + s0.y + b0.y) * (1.f / 3.f);
    r0.z = (wu * a0.z + s0.z + b0.z) * (1.f / 3.f);
    r0.w = (wu * a0.w + s0.w + b0.w) * (1.f / 3.f);
    r1.x = (wu * a1.x + s1.x + b1.x) * (1.f / 3.f);
    r1.y = (wu * a1.y + s1.y + b1.y) * (1.f / 3.f);
    r1.z = (wu * a1.z + s1.z + b1.z) * (1.f / 3.f);
    r1.w = (wu * a1.w + s1.w + b1.w) * (1.f / 3.f);
    *(float4*)(out + o)     = r0;
    *(float4*)(out + o + 4) = r1;
}

// de layer1: one weight vector, two srcs -> two outputs, octet nodes
__global__ void __launch_bounds__(256)
k_dual_s8(const int* __restrict__ csr, const int* __restrict__ off,
          const float* __restrict__ s0, const float* __restrict__ s1,
          const float* __restrict__ w,
          float* __restrict__ o0, float* __restrict__ o1, int ntot) {
    int wp = (blockIdx.x * blockDim.x + threadIdx.x) >> 5;
    int lane = threadIdx.x & 31;
    int q   = lane >> 2;
    int sub = lane & 3;
    int u = 8 * wp + q;
    int k = 0, end = 0;
    if (u < ntot) { k = off[u]; end = off[u + 1]; }
    float4 x0 = make_float4(0.f, 0.f, 0.f, 0.f), x1 = x0;
    float4 y0 = x0, y1 = x0;
    for (; k < end; k += 4) {
        int e[4]; float ww[4];
        #pragma unroll
        for (int j = 0; j < 4; j++) {
            int kk = k + j;
            e[j] = __ldg(&csr[kk < end ? kk : k]);
        }
        #pragma unroll
        for (int j = 0; j < 4; j++)
            ww[j] = (k + j < end) ? __ldg(&w[e[j]]) : 0.f;
        #pragma unroll
        for (int j = 0; j < 4; j++) {
            size_t rb = (size_t)e[j] * D;
            const float4* rp0 = (const float4*)(s0 + rb) + 2 * sub;
            const float4* rp1 = (const float4*)(s1 + rb) + 2 * sub;
            float4 va = __ldg(rp0);
            float4 vb = __ldg(rp0 + 1);
            float4 vc = __ldg(rp1);
            float4 vd = __ldg(rp1 + 1);
            fma4(x0, ww[j], va); fma4(x1, ww[j], vb);
            fma4(y0, ww[j], vc); fma4(y1, ww[j], vd);
        }
    }
    if (u >= ntot) return;
    size_t o = (size_t)u * D + 8 * sub;
    float wu = __ldg(&w[u]);
    *(float4*)(o0 + o)     = make_float4(wu * x0.x, wu * x0.y, wu * x0.z, wu * x0.w);
    *(float4*)(o0 + o + 4) = make_float4(wu * x1.x, wu * x1.y, wu * x1.z, wu * x1.w);
    *(float4*)(o1 + o)     = make_float4(wu * y0.x, wu * y0.y, wu * y0.z, wu * y0.w);
    *(float4*)(o1 + o + 4) = make_float4(wu * y1.x, wu * y1.y, wu * y1.z, wu * y1.w);
}

// ---------------------------------------------------------------------------
// Scoring (identical to R10)
// ---------------------------------------------------------------------------
__global__ void k_score_comb(const int* __restrict__ csrA0, const int* __restrict__ offA0,
                             const int* __restrict__ csrA1, const int* __restrict__ offA1,
                             const int* __restrict__ csrT, const int* __restrict__ offT,
                             const float* __restrict__ w0, const float* __restrict__ w1,
                             const float* __restrict__ nxt0, const float* __restrict__ nxt1,
                             const float* __restrict__ base,
                             const int* __restrict__ batch, int B, int nu) {
    int which = blockIdx.y;
    const int* csrA = which ? csrA1 : csrA0;
    const int* offA = which ? offA1 : offA0;
    const float* w   = which ? w1 : w0;
    const float* nxt = which ? nxt1 : nxt0;
    int wp = (blockIdx.x * blockDim.x + threadIdx.x) >> 5;
    if (wp >= B) return;
    int lane = threadIdx.x & 31;
    const int* row = batch + (size_t)wp * 9;
    int nd[3] = {row[0], nu + row[1], nu + row[2]};
    float val[3];
    #pragma unroll
    for (int t = 0; t < 3; t++) {
        int r = nd[t];
        float g = gather_w(csrA, offA[r], offA[r + 1], w, nxt, lane)
                + gather_w(csrT, offT[r], offT[r + 1], w, nxt, lane);
        size_t o = (size_t)r * D + lane;
        val[t] = base[o] + nxt[o] + __ldg(&w[r]) * g;
    }
    float pp = val[0] * val[1], nn = val[0] * val[2];
    #pragma unroll
    for (int o = 16; o; o >>= 1) {
        pp += __shfl_xor_sync(0xffffffffu, pp, o);
        nn += __shfl_xor_sync(0xffffffffu, nn, o);
    }
    if (lane == 0) {
        g_sc[(0 * 2 + which) * BMAX + wp] = fmaxf(pp * (1.f / 9.f), 0.f);
        g_sc[(1 * 2 + which) * BMAX + wp] = fmaxf(nn * (1.f / 9.f), 0.f);
    }
}

__global__ void k_score_de(const int* __restrict__ csrT, const int* __restrict__ offT,
                           const float* __restrict__ wT,
                           const float* __restrict__ d0, const float* __restrict__ d1,
                           const float* __restrict__ ae0, const float* __restrict__ ae1,
                           const int* __restrict__ batch, int B, int nu) {
    int wp = (blockIdx.x * blockDim.x + threadIdx.x) >> 5;
    if (wp >= B) return;
    int lane = threadIdx.x & 31;
    const int* row = batch + (size_t)wp * 9;
    int nd[3] = {row[0], nu + row[1], nu + row[2]};
    float v0[3], v1[3];
    #pragma unroll
    for (int t = 0; t < 3; t++) {
        int r = nd[t];
        int k = offT[r], end = offT[r + 1];
        float a0 = 0.f, a1 = 0.f;
        for (; k + 8 <= end; k += 8) {
            int e[8]; float wj[8];
            #pragma unroll
            for (int j = 0; j < 8; j++) e[j] = __ldg(&csrT[k + j]);
            #pragma unroll
            for (int j = 0; j < 8; j++) wj[j] = __ldg(&wT[e[j]]);
            #pragma unroll
            for (int j = 0; j < 8; j++) {
                size_t ro = (size_t)e[j] * D + lane;
                a0 = fmaf(wj[j], __ldg(&d0[ro]), a0);
                a1 = fmaf(wj[j], __ldg(&d1[ro]), a1);
            }
        }
        for (; k < end; k++) {
            int e = __ldg(&csrT[k]);
            float wj = __ldg(&wT[e]);
            size_t ro = (size_t)e * D + lane;
            a0 = fmaf(wj, __ldg(&d0[ro]), a0);
            a1 = fmaf(wj, __ldg(&d1[ro]), a1);
        }
        size_t o = (size_t)r * D + lane;
        float wr = __ldg(&wT[r]);
        v0[t] = ae0[o] + d0[o] + wr * a0;
        v1[t] = ae1[o] + d1[o] + wr * a1;
    }
    float pp0 = v0[0] * v0[1], nn0 = v0[0] * v0[2];
    float pp1 = v1[0] * v1[1], nn1 = v1[0] * v1[2];
    #pragma unroll
    for (int o = 16; o; o >>= 1) {
        pp0 += __shfl_xor_sync(0xffffffffu, pp0, o);
        nn0 += __shfl_xor_sync(0xffffffffu, nn0, o);
        pp1 += __shfl_xor_sync(0xffffffffu, pp1, o);
        nn1 += __shfl_xor_sync(0xffffffffu, nn1, o);
    }
    if (lane == 0) {
        g_sc[ 8 * BMAX + wp] = fmaxf(pp0 * (1.f / 9.f), 0.f);
        g_sc[10 * BMAX + wp] = fmaxf(nn0 * (1.f / 9.f), 0.f);
        g_sc[ 9 * BMAX + wp] = fmaxf(pp1 * (1.f / 9.f), 0.f);
        g_sc[11 * BMAX + wp] = fmaxf(nn1 * (1.f / 9.f), 0.f);
    }
}

__global__ void k_scores_aux2(const float* __restrict__ ae0, const float* __restrict__ ae1,
                              const int* __restrict__ batch, int B, int nu) {
    __shared__ float sh0[8], sh1[8];
    int warp = (blockIdx.x * blockDim.x + threadIdx.x) >> 5;
    int lane = threadIdx.x & 31;
    int wid  = threadIdx.x >> 5;
    float val0 = 0.f, val1 = 0.f;
    if (warp < B) {
        const int* row = batch + (size_t)warp * 9;
        int u = row[0], p = nu + row[1], n = nu + row[2];
        size_t ou = (size_t)u * D + lane, op = (size_t)p * D + lane, on = (size_t)n * D + lane;
        float e0u = ae0[ou], e1u = ae1[ou];
        float pp0 = e0u * ae0[op], nn0 = e0u * ae0[on];
        float pp1 = e1u * ae1[op], nn1 = e1u * ae1[on];
        const int* r0 = row + 3;
        const int* r1 = row + 6;
        float a0u = ae0[(size_t)r0[0] * D + lane];
        float ps0 = a0u * ae0[(size_t)(nu + r0[1]) * D + lane];
        float ns0 = a0u * ae0[(size_t)(nu + r0[2]) * D + lane];
        float a1u = ae1[(size_t)r1[0] * D + lane];
        float ps1 = a1u * ae1[(size_t)(nu + r1[1]) * D + lane];
        float ns1 = a1u * ae1[(size_t)(nu + r1[2]) * D + lane];
        #pragma unroll
        for (int o = 16; o; o >>= 1) {
            pp0 += __shfl_xor_sync(0xffffffffu, pp0, o);
            nn0 += __shfl_xor_sync(0xffffffffu, nn0, o);
            pp1 += __shfl_xor_sync(0xffffffffu, pp1, o);
            nn1 += __shfl_xor_sync(0xffffffffu, nn1, o);
            ps0 += __shfl_xor_sync(0xffffffffu, ps0, o);
            ns0 += __shfl_xor_sync(0xffffffffu, ns0, o);
            ps1 += __shfl_xor_sync(0xffffffffu, ps1, o);
            ns1 += __shfl_xor_sync(0xffffffffu, ns1, o);
        }
        if (lane == 0) {
            g_sc[4 * BMAX + warp] = fmaxf(pp0, 0.f);
            g_sc[6 * BMAX + warp] = fmaxf(nn0, 0.f);
            g_sc[5 * BMAX + warp] = fmaxf(pp1, 0.f);
            g_sc[7 * BMAX + warp] = fmaxf(nn1, 0.f);
        }
        val0 = logsig(ps0 - ns0);
        val1 = logsig(ps1 - ns1);
    }
    if (lane == 0) { sh0[wid] = val0; sh1[wid] = val1; }
    __syncthreads();
    if (threadIdx.x < 32) {
        float v0 = (threadIdx.x < (blockDim.x >> 5)) ? sh0[threadIdx.x] : 0.f;
        float v1 = (threadIdx.x < (blockDim.x >> 5)) ? sh1[threadIdx.x] : 0.f;
        #pragma unroll
        for (int o = 16; o; o >>= 1) {
            v0 += __shfl_xor_sync(0xffffffffu, v0, o);
            v1 += __shfl_xor_sync(0xffffffffu, v1, o);
        }
        if (threadIdx.x == 0) {
            atomicAdd(&g_scal[0], v0);
            atomicAdd(&g_scal[1], v1);
        }
    }
}

__global__ void k_sumsq2(const float* __restrict__ u, int nuD,
                         const float* __restrict__ it, int niD) {
    __shared__ float sh[8];
    const float* x = blockIdx.y ? it : u;
    int n = blockIdx.y ? niD : nuD;
    int slot = blockIdx.y ? 3 : 2;
    float local = 0.f;
    for (int i = blockIdx.x * blockDim.x + threadIdx.x; i < n; i += gridDim.x * blockDim.x) {
        float v = x[i];
        local += v * v;
    }
    int lane = threadIdx.x & 31, wid = threadIdx.x >> 5;
    #pragma unroll
    for (int o = 16; o; o >>= 1) local += __shfl_xor_sync(0xffffffffu, local, o);
    if (lane == 0) sh[wid] = local;
    __syncthreads();
    if (threadIdx.x < 32) {
        float v = (threadIdx.x < (blockDim.x >> 5)) ? sh[threadIdx.x] : 0.f;
        #pragma unroll
        for (int o = 16; o; o >>= 1) v += __shfl_xor_sync(0xffffffffu, v, o);
        if (threadIdx.x == 0) atomicAdd(&g_scal[slot], v);
    }
}

__global__ void k_final(int B, int ni, float* __restrict__ out) {
    __shared__ float sh[8];
    float local = 0.f;
    for (int b = threadIdx.x; b < B; b += blockDim.x) {
        float cp0 = g_sc[ 0 * BMAX + b], cp1 = g_sc[ 1 * BMAX + b];
        float cn0 = g_sc[ 2 * BMAX + b], cn1 = g_sc[ 3 * BMAX + b];
        float ap0 = g_sc[ 4 * BMAX + b], ap1 = g_sc[ 5 * BMAX + b];
        float an0 = g_sc[ 6 * BMAX + b], an1 = g_sc[ 7 * BMAX + b];
        float dp0 = g_sc[ 8 * BMAX + b], dp1 = g_sc[ 9 * BMAX + b];
        float dn0 = g_sc[10 * BMAX + b], dn1 = g_sc[11 * BMAX + b];
        float ps = (dp0 + dp1) * (cp0 * ap0 + cp1 * ap1);
        float ns = (dn0 + dn1) * (cn0 * an0 + cn1 * an1);
        local += logsig(ps - ns);
    }
    int lane = threadIdx.x & 31, wid = threadIdx.x >> 5;
    #pragma unroll
    for (int o = 16; o; o >>= 1) local += __shfl_xor_sync(0xffffffffu, local, o);
    if (lane == 0) sh[wid] = local;
    __syncthreads();
    if (threadIdx.x == 0) {
        float s = 0.f;
        for (int i = 0; i < (int)(blockDim.x >> 5); i++) s += sh[i];
        float rec  = -s / (float)B;
        float aux  = -(g_scal[0] + g_scal[1]) / (2.f * (float)B);
        float embl = (sqrtf(g_scal[2]) + sqrtf(g_scal[3])) / (float)ni;
        out[0] = rec + 0.5f * aux + 1e-4f * embl;
    }
}

// ---------------------------------------------------------------------------
// Host orchestration (graph-capturable, fork/join dual stream)
// ---------------------------------------------------------------------------
#define TB 256
static inline int nblk(long long n) { return (int)((n + TB - 1) / TB); }

extern "C" void kernel_launch(void* const* d_in, const int* in_sizes, int n_in,
                              void* d_out, int out_size) {
    static cudaStream_t s1 = 0;
    static cudaEvent_t e0 = 0, e1 = 0, e2 = 0, e3 = 0;
    if (!s1) {
        cudaStreamCreateWithFlags(&s1, cudaStreamNonBlocking);
        cudaEventCreateWithFlags(&e0, cudaEventDisableTiming);
        cudaEventCreateWithFlags(&e1, cudaEventDisableTiming);
        cudaEventCreateWithFlags(&e2, cudaEventDisableTiming);
        cudaEventCreateWithFlags(&e3, cudaEventDisableTiming);
    }

    const float* user  = (const float*)d_in[0];
    const float* item  = (const float*)d_in[1];
    const int*   batch = (const int*)  d_in[2];
    const int2*  aux   = (const int2*) d_in[3];
    const int2*  tgt   = (const int2*) d_in[4];

    const int nu   = in_sizes[0] / D;
    const int ni   = in_sizes[1] / D;
    const int ntot = nu + ni;
    const int B    = in_sizes[2] / 9;
    const int Ea   = in_sizes[3] / 4;
    const int Et   = in_sizes[4] / 2;

    float *emb, *pc0, *pc1, *ae0, *ae1, *a0, *a1, *dnv;
    float2* dnv2;
    int *degi, *off, *curs, *csr;
    void* p;
    cudaGetSymbolAddress(&p, g_emb);  emb = (float*)p;
    cudaGetSymbolAddress(&p, g_pc0);  pc0 = (float*)p;
    cudaGetSymbolAddress(&p, g_pc1);  pc1 = (float*)p;
    cudaGetSymbolAddress(&p, g_ae0);  ae0 = (float*)p;
    cudaGetSymbolAddress(&p, g_ae1);  ae1 = (float*)p;
    cudaGetSymbolAddress(&p, g_a0);   a0  = (float*)p;
    cudaGetSymbolAddress(&p, g_a1);   a1  = (float*)p;
    cudaGetSymbolAddress(&p, g_dnv);  dnv = (float*)p;
    cudaGetSymbolAddress(&p, g_dnv2); dnv2 = (float2*)p;
    cudaGetSymbolAddress(&p, g_degi); degi = (int*)p;
    cudaGetSymbolAddress(&p, g_off);  off  = (int*)p;
    cudaGetSymbolAddress(&p, g_curs); curs = (int*)p;
    cudaGetSymbolAddress(&p, g_csr);  csr  = (int*)p;
    void* scalp; cudaGetSymbolAddress(&scalp, g_scal);

    const float* wC0 = dnv + 0 * NTOT_C;
    const float* wC1 = dnv + 1 * NTOT_C;
    const float* wA0 = dnv + 2 * NTOT_C;
    const float* wA1 = dnv + 3 * NTOT_C;
    const float* wT  = dnv + 4 * NTOT_C;

    // ---- init + fork sumsq to side stream ----
    cudaMemsetAsync(scalp, 0, 4 * sizeof(float), 0);
    cudaEventRecord(e0, 0);
    cudaStreamWaitEvent(s1, e0, 0);
    {
        dim3 g(512, 2);
        k_sumsq2<<<g, TB, 0, s1>>>(user, nu * D, item, ni * D);
    }
    cudaMemcpyAsync(emb, user, (size_t)nu * D * sizeof(float), cudaMemcpyDeviceToDevice, 0);
    cudaMemcpyAsync(emb + (size_t)nu * D, item, (size_t)ni * D * sizeof(float),
                    cudaMemcpyDeviceToDevice, 0);

    // ---- build ----
    cudaMemsetAsync(degi, 0, 3 * NTOT_C * sizeof(int), 0);
    k_deg3<<<nblk(2LL * Ea + Et), TB>>>(aux, tgt, Ea, Et, nu);
    k_dinv5<<<nblk(NTOT_C), TB>>>();
    dim3 gScan(NBLK_SCAN, 3);
    k_scanA<<<gScan, SCAN_B>>>();
    k_scanB<<<3, 1024>>>(NBLK_SCAN);
    k_scanC<<<gScan, SCAN_B>>>();
    cudaMemcpyAsync(curs, off, 3 * NOFF * sizeof(int), cudaMemcpyDeviceToDevice, 0);
    k_fill3<<<nblk(2LL * Ea + Et), TB>>>(aux, tgt, Ea, Et, nu);

    const long long bA0 = 0, bA1 = 2LL * Ea, bT = 4LL * Ea;
    const int* offA0 = off + 0 * NOFF;
    const int* offA1 = off + 1 * NOFF;
    const int* offT  = off + 2 * NOFF;
    const int noct  = (ntot + 7) / 8;
    const int gcnB8 = nblk((long long)noct * 32);
    const int sblk  = nblk((long long)B * 32);

    // ---- layer-1 (octet-node dual-weight; tgt pass accumulates) ----
    k_dual_w8<<<gcnB8, TB>>>(csr + bA0, offA0, emb, dnv2 + 0 * NTOT_C, wC0, wA0,
                             pc0, a0, ntot, 0);
    k_dual_w8<<<gcnB8, TB>>>(csr + bA1, offA1, emb, dnv2 + 1 * NTOT_C, wC1, wA1,
                             pc1, a1, ntot, 0);
    k_dual_w8<<<gcnB8, TB>>>(csr + bT,  offT,  emb, dnv2 + 2 * NTOT_C, wC0, wC1,
                             pc0, pc1, ntot, 1);

    // fork comb scoring to side stream
    cudaEventRecord(e1, 0);
    cudaStreamWaitEvent(s1, e1, 0);
    {
        dim3 g(sblk, 2);
        k_score_comb<<<g, TB, 0, s1>>>(csr + bA0, offA0, csr + bA1, offA1,
                                       csr + bT, offT, wC0, wC1, pc0, pc1, emb,
                                       batch, B, nu);
    }

    // ---- aux layer-2 -> ae (octet nodes) ----
    k_gcn_w8<<<gcnB8, TB>>>(csr + bA0, offA0, wA0, a0, emb, ae0, ntot);
    k_gcn_w8<<<gcnB8, TB>>>(csr + bA1, offA1, wA1, a1, emb, ae1, ntot);

    // fork aux scores to side stream
    cudaEventRecord(e2, 0);
    cudaStreamWaitEvent(s1, e2, 0);
    k_scores_aux2<<<sblk, TB, 0, s1>>>(ae0, ae1, batch, B, nu);

    // ---- de layer-1 (octet nodes, dual source) + de scoring ----
    float* d0 = a0;
    float* d1 = a1;
    k_dual_s8<<<gcnB8, TB>>>(csr + bT, offT, ae0, ae1, wT, d0, d1, ntot);
    k_score_de<<<sblk, TB>>>(csr + bT, offT, wT, d0, d1, ae0, ae1, batch, B, nu);

    // ---- join + finalize ----
    cudaEventRecord(e3, s1);
    cudaStreamWaitEvent(0, e3, 0);
    k_final<<<1, TB>>>(B, ni, (float*)d_out);
}

// round 17
// speedup vs baseline: 1.0097x; 1.0097x over previous
#include <cuda_runtime.h>
#include <math.h>

// ---------------------------------------------------------------------------
// Shapes
// ---------------------------------------------------------------------------
#define D        32
#define NU_C     100001
#define NI_C     50001
#define NTOT_C   (NU_C + NI_C)          // 150002
#define NOFF     (NTOT_C + 1)
#define BMAX     4096
#define SCAN_B   256
#define NBLK_SCAN ((NOFF + SCAN_B - 1) / SCAN_B)
#define SUMS_STRIDE 640
#define CSR_CAP  6400000

// ---------------------------------------------------------------------------
// Device scratch
// ---------------------------------------------------------------------------
__device__ float g_emb[NTOT_C * D];
__device__ float g_pc0[NTOT_C * D];     // comb0 layer1
__device__ float g_pc1[NTOT_C * D];     // comb1 layer1
__device__ float g_ae0[NTOT_C * D];     // ae0
__device__ float g_ae1[NTOT_C * D];     // ae1
__device__ float g_a0 [NTOT_C * D];     // aux0 layer1; later de0 layer1
__device__ float g_a1 [NTOT_C * D];     // aux1 layer1; later de1 layer1
__device__ int    g_degi [3 * NTOT_C];  // aux0, aux1, tgt
__device__ float  g_dnv  [5 * NTOT_C];  // SoA: c0, c1, a0, a1, t
__device__ float2 g_dnv2 [3 * NTOT_C];  // pairs: (c0,a0), (c1,a1), (c0,c1)
__device__ int   g_off  [3 * NOFF];
__device__ int   g_curs [3 * NOFF];
__device__ int   g_bsums[3 * SUMS_STRIDE];
__device__ int   g_csr  [CSR_CAP];      // neighbor indices only
// score slots: CP=0 CN=1 AP=2 AN=3 DP=4 DN=5; offset = (slot*2 + idx)*BMAX + b
__device__ float g_sc  [12 * BMAX];
__device__ float g_scal[4];

// ---------------------------------------------------------------------------
// Helpers
// ---------------------------------------------------------------------------
__device__ __forceinline__ float logsig(float x) {
    return (x >= 0.f) ? -log1pf(expf(-x)) : (x - log1pf(expf(x)));
}

__device__ __forceinline__ void fma4(float4& a, float w, float4 v) {
    a.x = fmaf(w, v.x, a.x);
    a.y = fmaf(w, v.y, a.y);
    a.z = fmaf(w, v.z, a.z);
    a.w = fmaf(w, v.w, a.w);
}

__device__ __forceinline__ float dot4(float4 a, float4 b) {
    return a.x * b.x + a.y * b.y + a.z * b.z + a.w * b.w;
}

// warp-per-row weighted gather (comb scoring; R10-proven shape)
__device__ __forceinline__ float gather_w(const int* __restrict__ csr,
                                          int k, int end,
                                          const float* __restrict__ dnv,
                                          const float* __restrict__ src,
                                          int lane) {
    float acc = 0.f;
    for (; k + 8 <= end; k += 8) {
        int e[8]; float w[8];
        #pragma unroll
        for (int j = 0; j < 8; j++) e[j] = __ldg(&csr[k + j]);
        #pragma unroll
        for (int j = 0; j < 8; j++) w[j] = __ldg(&dnv[e[j]]);
        #pragma unroll
        for (int j = 0; j < 8; j++)
            acc = fmaf(w[j], __ldg(&src[(size_t)e[j] * D + lane]), acc);
    }
    for (; k < end; k++) {
        int e = __ldg(&csr[k]);
        acc = fmaf(__ldg(&dnv[e]), __ldg(&src[(size_t)e * D + lane]), acc);
    }
    return acc;
}

// ---------------------------------------------------------------------------
// Graph build
// ---------------------------------------------------------------------------
__global__ void k_deg3(const int2* __restrict__ aux, const int2* __restrict__ tgt,
                       int Ea, int Et, int nu) {
    int t = blockIdx.x * blockDim.x + threadIdx.x;
    int2 ed; int slot;
    if (t < 2 * Ea)            { ed = aux[t];          slot = (t < Ea) ? 0 : 1; }
    else if (t < 2 * Ea + Et)  { ed = tgt[t - 2 * Ea]; slot = 2; }
    else return;
    int* deg = g_degi + slot * NTOT_C;
    atomicAdd(&deg[ed.x], 1);
    atomicAdd(&deg[nu + ed.y], 1);
}

__global__ void k_dinv5() {
    int i = blockIdx.x * blockDim.x + threadIdx.x;
    if (i >= NTOT_C) return;
    int d0 = g_degi[0 * NTOT_C + i];
    int d1 = g_degi[1 * NTOT_C + i];
    int dt = g_degi[2 * NTOT_C + i];
    int dd[5] = {d0 + dt, d1 + dt, d0, d1, dt};
    float w[5];
    #pragma unroll
    for (int s = 0; s < 5; s++) {
        w[s] = (dd[s] > 0) ? rsqrtf((float)dd[s]) : 0.f;
        g_dnv[s * NTOT_C + i] = w[s];
    }
    g_dnv2[0 * NTOT_C + i] = make_float2(w[0], w[2]);  // (c0, a0)
    g_dnv2[1 * NTOT_C + i] = make_float2(w[1], w[3]);  // (c1, a1)
    g_dnv2[2 * NTOT_C + i] = make_float2(w[0], w[1]);  // (c0, c1)
}

__global__ void k_scanA() {
    int g = blockIdx.y;
    const int* deg = g_degi + g * NTOT_C;
    int* out  = g_off   + g * NOFF;
    int* sums = g_bsums + g * SUMS_STRIDE;
    int idx = blockIdx.x * SCAN_B + threadIdx.x;
    int val = (idx < NTOT_C) ? deg[idx] : 0;
    int lane = threadIdx.x & 31, wid = threadIdx.x >> 5;
    int x = val;
    #pragma unroll
    for (int o = 1; o < 32; o <<= 1) {
        int y = __shfl_up_sync(0xffffffffu, x, o);
        if (lane >= o) x += y;
    }
    __shared__ int ws[8], wbase[8];
    if (lane == 31) ws[wid] = x;
    __syncthreads();
    if (threadIdx.x == 0) {
        int s = 0;
        for (int i = 0; i < 8; i++) { wbase[i] = s; s += ws[i]; }
    }
    __syncthreads();
    int incl = x + wbase[wid];
    if (idx < NOFF) out[idx] = incl - val;
    if (threadIdx.x == SCAN_B - 1) sums[blockIdx.x] = incl;
}

__global__ void k_scanB(int nb) {
    int g = blockIdx.x;
    int* sums = g_bsums + g * SUMS_STRIDE;
    __shared__ int sh[SUMS_STRIDE];
    int tid = threadIdx.x;
    int orig = 0;
    if (tid < nb) { orig = sums[tid]; sh[tid] = orig; }
    __syncthreads();
    for (int o = 1; o < nb; o <<= 1) {
        int v = 0;
        if (tid < nb && tid >= o) v = sh[tid - o];
        __syncthreads();
        if (tid < nb && tid >= o) sh[tid] += v;
        __syncthreads();
    }
    if (tid < nb) sums[tid] = sh[tid] - orig;
}

__global__ void k_scanC() {
    int g = blockIdx.y;
    int idx = blockIdx.x * SCAN_B + threadIdx.x;
    if (idx < NOFF)
        g_off[g * NOFF + idx] += g_bsums[g * SUMS_STRIDE + blockIdx.x];
}

__global__ void k_fill_aux(const int2* __restrict__ aux, int Ea, int nu) {
    int t = blockIdx.x * blockDim.x + threadIdx.x;
    if (t >= 2 * Ea) return;
    int slot = (t < Ea) ? 0 : 1;
    long long base = (t < Ea) ? 0 : 2LL * Ea;
    int2 ed = aux[t];
    int* curs = g_curs + slot * NOFF;
    int* csr  = g_csr + base;
    int u = ed.x, v = nu + ed.y;
    csr[atomicAdd(&curs[u], 1)] = v;
    csr[atomicAdd(&curs[v], 1)] = u;
}

__global__ void k_fill_tgt(const int2* __restrict__ tgt, int Et, long long base, int nu) {
    int t = blockIdx.x * blockDim.x + threadIdx.x;
    if (t >= Et) return;
    int2 ed = tgt[t];
    int* curs = g_curs + 2 * NOFF;
    int* csr  = g_csr + base;
    int u = ed.x, v = nu + ed.y;
    csr[atomicAdd(&curs[u], 1)] = v;
    csr[atomicAdd(&curs[v], 1)] = u;
}

// ---------------------------------------------------------------------------
// Propagation — FOUR nodes per warp, float4 columns (R15-proven)
// lanes [8q, 8q+8) -> node 4w+q; each lane covers cols 4s..4s+3 (s = lane&7)
// ---------------------------------------------------------------------------
__global__ void __launch_bounds__(256)
k_dual_w4(const int* __restrict__ csr, const int* __restrict__ off,
          const float* __restrict__ src,
          const float2* __restrict__ w2,
          const float* __restrict__ wXs, const float* __restrict__ wYs,
          float* __restrict__ outX, float* __restrict__ outY, int ntot, int accum) {
    int w = (blockIdx.x * blockDim.x + threadIdx.x) >> 5;
    int lane = threadIdx.x & 31;
    int q   = lane >> 3;
    int sub = lane & 7;
    int u = 4 * w + q;
    int k = 0, end = 0;
    if (u < ntot) { k = off[u]; end = off[u + 1]; }
    float4 aX = make_float4(0.f, 0.f, 0.f, 0.f);
    float4 aY = make_float4(0.f, 0.f, 0.f, 0.f);
    for (; k < end; k += 8) {
        int e[8]; float2 ww[8];
        #pragma unroll
        for (int j = 0; j < 8; j++) {
            int kk = k + j;
            e[j] = __ldg(&csr[kk < end ? kk : k]);
        }
        #pragma unroll
        for (int j = 0; j < 8; j++)
            ww[j] = (k + j < end) ? __ldg(&w2[e[j]]) : make_float2(0.f, 0.f);
        #pragma unroll
        for (int j = 0; j < 8; j++) {
            float4 v = __ldg((const float4*)(src + (size_t)e[j] * D) + sub);
            fma4(aX, ww[j].x, v);
            fma4(aY, ww[j].y, v);
        }
    }
    if (u >= ntot) return;
    size_t o = (size_t)u * D + 4 * sub;
    float sx = __ldg(&wXs[u]);
    float sy = __ldg(&wYs[u]);
    float4 rx = make_float4(sx * aX.x, sx * aX.y, sx * aX.z, sx * aX.w);
    float4 ry = make_float4(sy * aY.x, sy * aY.y, sy * aY.z, sy * aY.w);
    if (accum) {
        float4 px = *(const float4*)(outX + o);
        float4 py = *(const float4*)(outY + o);
        rx.x += px.x; rx.y += px.y; rx.z += px.z; rx.w += px.w;
        ry.x += py.x; ry.y += py.y; ry.z += py.z; ry.w += py.w;
    }
    *(float4*)(outX + o) = rx;
    *(float4*)(outY + o) = ry;
}

__global__ void __launch_bounds__(256)
k_gcn_w4(const int* __restrict__ csr, const int* __restrict__ off,
         const float* __restrict__ w,
         const float* __restrict__ src, const float* __restrict__ base,
         float* __restrict__ out, int ntot) {
    int wp = (blockIdx.x * blockDim.x + threadIdx.x) >> 5;
    int lane = threadIdx.x & 31;
    int q   = lane >> 3;
    int sub = lane & 7;
    int u = 4 * wp + q;
    int k = 0, end = 0;
    if (u < ntot) { k = off[u]; end = off[u + 1]; }
    float4 acc = make_float4(0.f, 0.f, 0.f, 0.f);
    for (; k < end; k += 8) {
        int e[8]; float ww[8];
        #pragma unroll
        for (int j = 0; j < 8; j++) {
            int kk = k + j;
            e[j] = __ldg(&csr[kk < end ? kk : k]);
        }
        #pragma unroll
        for (int j = 0; j < 8; j++)
            ww[j] = (k + j < end) ? __ldg(&w[e[j]]) : 0.f;
        #pragma unroll
        for (int j = 0; j < 8; j++) {
            float4 v = __ldg((const float4*)(src + (size_t)e[j] * D) + sub);
            fma4(acc, ww[j], v);
        }
    }
    if (u >= ntot) return;
    size_t o = (size_t)u * D + 4 * sub;
    float wu = __ldg(&w[u]);
    float4 s = *(const float4*)(src + o);
    float4 b = *(const float4*)(base + o);
    float4 r;
    r.x = (wu * acc.x + s.x + b.x) * (1.f / 3.f);
    r.y = (wu * acc.y + s.y + b.y) * (1.f / 3.f);
    r.z = (wu * acc.z + s.z + b.z) * (1.f / 3.f);
    r.w = (wu * acc.w + s.w + b.w) * (1.f / 3.f);
    *(float4*)(out + o) = r;
}

__global__ void __launch_bounds__(256)
k_dual_s4(const int* __restrict__ csr, const int* __restrict__ off,
          const float* __restrict__ s0, const float* __restrict__ s1,
          const float* __restrict__ w,
          float* __restrict__ o0, float* __restrict__ o1, int ntot) {
    int wp = (blockIdx.x * blockDim.x + threadIdx.x) >> 5;
    int lane = threadIdx.x & 31;
    int q   = lane >> 3;
    int sub = lane & 7;
    int u = 4 * wp + q;
    int k = 0, end = 0;
    if (u < ntot) { k = off[u]; end = off[u + 1]; }
    float4 a0 = make_float4(0.f, 0.f, 0.f, 0.f);
    float4 a1 = make_float4(0.f, 0.f, 0.f, 0.f);
    for (; k < end; k += 8) {
        int e[8]; float ww[8];
        #pragma unroll
        for (int j = 0; j < 8; j++) {
            int kk = k + j;
            e[j] = __ldg(&csr[kk < end ? kk : k]);
        }
        #pragma unroll
        for (int j = 0; j < 8; j++)
            ww[j] = (k + j < end) ? __ldg(&w[e[j]]) : 0.f;
        #pragma unroll
        for (int j = 0; j < 8; j++) {
            size_t rb = (size_t)e[j] * D;
            float4 v0 = __ldg((const float4*)(s0 + rb) + sub);
            float4 v1 = __ldg((const float4*)(s1 + rb) + sub);
            fma4(a0, ww[j], v0);
            fma4(a1, ww[j], v1);
        }
    }
    if (u >= ntot) return;
    size_t o = (size_t)u * D + 4 * sub;
    float wu = __ldg(&w[u]);
    *(float4*)(o0 + o) = make_float4(wu * a0.x, wu * a0.y, wu * a0.z, wu * a0.w);
    *(float4*)(o1 + o) = make_float4(wu * a1.x, wu * a1.y, wu * a1.z, wu * a1.w);
}

// ---------------------------------------------------------------------------
// Scoring
// ---------------------------------------------------------------------------
__global__ void k_score_comb(const int* __restrict__ csrA0, const int* __restrict__ offA0,
                             const int* __restrict__ csrA1, const int* __restrict__ offA1,
                             const int* __restrict__ csrT, const int* __restrict__ offT,
                             const float* __restrict__ w0, const float* __restrict__ w1,
                             const float* __restrict__ nxt0, const float* __restrict__ nxt1,
                             const float* __restrict__ base,
                             const int* __restrict__ batch, int B, int nu) {
    int which = blockIdx.y;
    const int* csrA = which ? csrA1 : csrA0;
    const int* offA = which ? offA1 : offA0;
    const float* w   = which ? w1 : w0;
    const float* nxt = which ? nxt1 : nxt0;
    int wp = (blockIdx.x * blockDim.x + threadIdx.x) >> 5;
    if (wp >= B) return;
    int lane = threadIdx.x & 31;
    const int* row = batch + (size_t)wp * 9;
    int nd[3] = {row[0], nu + row[1], nu + row[2]};
    float val[3];
    #pragma unroll
    for (int t = 0; t < 3; t++) {
        int r = nd[t];
        float g = gather_w(csrA, offA[r], offA[r + 1], w, nxt, lane)
                + gather_w(csrT, offT[r], offT[r + 1], w, nxt, lane);
        size_t o = (size_t)r * D + lane;
        val[t] = base[o] + nxt[o] + __ldg(&w[r]) * g;
    }
    float pp = val[0] * val[1], nn = val[0] * val[2];
    #pragma unroll
    for (int o = 16; o; o >>= 1) {
        pp += __shfl_xor_sync(0xffffffffu, pp, o);
        nn += __shfl_xor_sync(0xffffffffu, nn, o);
    }
    if (lane == 0) {
        g_sc[(0 * 2 + which) * BMAX + wp] = fmaxf(pp * (1.f / 9.f), 0.f);
        g_sc[(1 * 2 + which) * BMAX + wp] = fmaxf(nn * (1.f / 9.f), 0.f);
    }
}

// de scoring, quad-packed: 4 batch rows per warp, 8 lanes/row, float4 cols
__global__ void k_score_de4(const int* __restrict__ csrT, const int* __restrict__ offT,
                            const float* __restrict__ wT,
                            const float* __restrict__ d0, const float* __restrict__ d1,
                            const float* __restrict__ ae0, const float* __restrict__ ae1,
                            const int* __restrict__ batch, int B, int nu) {
    int w = (blockIdx.x * blockDim.x + threadIdx.x) >> 5;
    int lane = threadIdx.x & 31;
    int g   = lane >> 3;   // row within warp
    int sub = lane & 7;    // col quad
    int wp = 4 * w + g;
    if (wp >= B) return;
    const int* row = batch + (size_t)wp * 9;
    int nd[3] = {row[0], nu + row[1], nu + row[2]};
    float4 v0[3], v1[3];
    #pragma unroll
    for (int t = 0; t < 3; t++) {
        int r = nd[t];
        int k = offT[r], end = offT[r + 1];
        float4 a0 = make_float4(0.f, 0.f, 0.f, 0.f);
        float4 a1 = make_float4(0.f, 0.f, 0.f, 0.f);
        for (; k < end; k += 4) {
            int e[4]; float ww[4];
            #pragma unroll
            for (int j = 0; j < 4; j++) {
                int kk = k + j;
                e[j] = __ldg(&csrT[kk < end ? kk : k]);
            }
            #pragma unroll
            for (int j = 0; j < 4; j++)
                ww[j] = (k + j < end) ? __ldg(&wT[e[j]]) : 0.f;
            #pragma unroll
            for (int j = 0; j < 4; j++) {
                size_t rb = (size_t)e[j] * D;
                float4 x0 = __ldg((const float4*)(d0 + rb) + sub);
                float4 x1 = __ldg((const float4*)(d1 + rb) + sub);
                fma4(a0, ww[j], x0);
                fma4(a1, ww[j], x1);
            }
        }
        size_t o = (size_t)r * D + 4 * sub;
        float wr = __ldg(&wT[r]);
        float4 e0 = *(const float4*)(ae0 + o);
        float4 dd0 = *(const float4*)(d0 + o);
        float4 e1 = *(const float4*)(ae1 + o);
        float4 dd1 = *(const float4*)(d1 + o);
        v0[t] = make_float4(e0.x + dd0.x + wr * a0.x, e0.y + dd0.y + wr * a0.y,
                            e0.z + dd0.z + wr * a0.z, e0.w + dd0.w + wr * a0.w);
        v1[t] = make_float4(e1.x + dd1.x + wr * a1.x, e1.y + dd1.y + wr * a1.y,
                            e1.z + dd1.z + wr * a1.z, e1.w + dd1.w + wr * a1.w);
    }
    float pp0 = dot4(v0[0], v0[1]), nn0 = dot4(v0[0], v0[2]);
    float pp1 = dot4(v1[0], v1[1]), nn1 = dot4(v1[0], v1[2]);
    #pragma unroll
    for (int o = 4; o; o >>= 1) {
        pp0 += __shfl_xor_sync(0xffffffffu, pp0, o);
        nn0 += __shfl_xor_sync(0xffffffffu, nn0, o);
        pp1 += __shfl_xor_sync(0xffffffffu, pp1, o);
        nn1 += __shfl_xor_sync(0xffffffffu, nn1, o);
    }
    if (sub == 0) {
        g_sc[ 8 * BMAX + wp] = fmaxf(pp0 * (1.f / 9.f), 0.f);
        g_sc[10 * BMAX + wp] = fmaxf(nn0 * (1.f / 9.f), 0.f);
        g_sc[ 9 * BMAX + wp] = fmaxf(pp1 * (1.f / 9.f), 0.f);
        g_sc[11 * BMAX + wp] = fmaxf(nn1 * (1.f / 9.f), 0.f);
    }
}

__global__ void k_scores_aux2(const float* __restrict__ ae0, const float* __restrict__ ae1,
                              const int* __restrict__ batch, int B, int nu) {
    __shared__ float sh0[8], sh1[8];
    int warp = (blockIdx.x * blockDim.x + threadIdx.x) >> 5;
    int lane = threadIdx.x & 31;
    int wid  = threadIdx.x >> 5;
    float val0 = 0.f, val1 = 0.f;
    if (warp < B) {
        const int* row = batch + (size_t)warp * 9;
        int u = row[0], p = nu + row[1], n = nu + row[2];
        size_t ou = (size_t)u * D + lane, op = (size_t)p * D + lane, on = (size_t)n * D + lane;
        float e0u = ae0[ou], e1u = ae1[ou];
        float pp0 = e0u * ae0[op], nn0 = e0u * ae0[on];
        float pp1 = e1u * ae1[op], nn1 = e1u * ae1[on];
        const int* r0 = row + 3;
        const int* r1 = row + 6;
        float a0u = ae0[(size_t)r0[0] * D + lane];
        float ps0 = a0u * ae0[(size_t)(nu + r0[1]) * D + lane];
        float ns0 = a0u * ae0[(size_t)(nu + r0[2]) * D + lane];
        float a1u = ae1[(size_t)r1[0] * D + lane];
        float ps1 = a1u * ae1[(size_t)(nu + r1[1]) * D + lane];
        float ns1 = a1u * ae1[(size_t)(nu + r1[2]) * D + lane];
        #pragma unroll
        for (int o = 16; o; o >>= 1) {
            pp0 += __shfl_xor_sync(0xffffffffu, pp0, o);
            nn0 += __shfl_xor_sync(0xffffffffu, nn0, o);
            pp1 += __shfl_xor_sync(0xffffffffu, pp1, o);
            nn1 += __shfl_xor_sync(0xffffffffu, nn1, o);
            ps0 += __shfl_xor_sync(0xffffffffu, ps0, o);
            ns0 += __shfl_xor_sync(0xffffffffu, ns0, o);
            ps1 += __shfl_xor_sync(0xffffffffu, ps1, o);
            ns1 += __shfl_xor_sync(0xffffffffu, ns1, o);
        }
        if (lane == 0) {
            g_sc[4 * BMAX + warp] = fmaxf(pp0, 0.f);
            g_sc[6 * BMAX + warp] = fmaxf(nn0, 0.f);
            g_sc[5 * BMAX + warp] = fmaxf(pp1, 0.f);
            g_sc[7 * BMAX + warp] = fmaxf(nn1, 0.f);
        }
        val0 = logsig(ps0 - ns0);
        val1 = logsig(ps1 - ns1);
    }
    if (lane == 0) { sh0[wid] = val0; sh1[wid] = val1; }
    __syncthreads();
    if (threadIdx.x < 32) {
        float v0 = (threadIdx.x < (blockDim.x >> 5)) ? sh0[threadIdx.x] : 0.f;
        float v1 = (threadIdx.x < (blockDim.x >> 5)) ? sh1[threadIdx.x] : 0.f;
        #pragma unroll
        for (int o = 16; o; o >>= 1) {
            v0 += __shfl_xor_sync(0xffffffffu, v0, o);
            v1 += __shfl_xor_sync(0xffffffffu, v1, o);
        }
        if (threadIdx.x == 0) {
            atomicAdd(&g_scal[0], v0);
            atomicAdd(&g_scal[1], v1);
        }
    }
}

__global__ void k_sumsq2(const float* __restrict__ u, int nuD,
                         const float* __restrict__ it, int niD) {
    __shared__ float sh[8];
    const float* x = blockIdx.y ? it : u;
    int n = blockIdx.y ? niD : nuD;
    int slot = blockIdx.y ? 3 : 2;
    float local = 0.f;
    for (int i = blockIdx.x * blockDim.x + threadIdx.x; i < n; i += gridDim.x * blockDim.x) {
        float v = x[i];
        local += v * v;
    }
    int lane = threadIdx.x & 31, wid = threadIdx.x >> 5;
    #pragma unroll
    for (int o = 16; o; o >>= 1) local += __shfl_xor_sync(0xffffffffu, local, o);
    if (lane == 0) sh[wid] = local;
    __syncthreads();
    if (threadIdx.x < 32) {
        float v = (threadIdx.x < (blockDim.x >> 5)) ? sh[threadIdx.x] : 0.f;
        #pragma unroll
        for (int o = 16; o; o >>= 1) v += __shfl_xor_sync(0xffffffffu, v, o);
        if (threadIdx.x == 0) atomicAdd(&g_scal[slot], v);
    }
}

__global__ void k_final(int B, int ni, float* __restrict__ out) {
    __shared__ float sh[8];
    float local = 0.f;
    for (int b = threadIdx.x; b < B; b += blockDim.x) {
        float cp0 = g_sc[ 0 * BMAX + b], cp1 = g_sc[ 1 * BMAX + b];
        float cn0 = g_sc[ 2 * BMAX + b], cn1 = g_sc[ 3 * BMAX + b];
        float ap0 = g_sc[ 4 * BMAX + b], ap1 = g_sc[ 5 * BMAX + b];
        float an0 = g_sc[ 6 * BMAX + b], an1 = g_sc[ 7 * BMAX + b];
        float dp0 = g_sc[ 8 * BMAX + b], dp1 = g_sc[ 9 * BMAX + b];
        float dn0 = g_sc[10 * BMAX + b], dn1 = g_sc[11 * BMAX + b];
        float ps = (dp0 + dp1) * (cp0 * ap0 + cp1 * ap1);
        float ns = (dn0 + dn1) * (cn0 * an0 + cn1 * an1);
        local += logsig(ps - ns);
    }
    int lane = threadIdx.x & 31, wid = threadIdx.x >> 5;
    #pragma unroll
    for (int o = 16; o; o >>= 1) local += __shfl_xor_sync(0xffffffffu, local, o);
    if (lane == 0) sh[wid] = local;
    __syncthreads();
    if (threadIdx.x == 0) {
        float s = 0.f;
        for (int i = 0; i < (int)(blockDim.x >> 5); i++) s += sh[i];
        float rec  = -s / (float)B;
        float aux  = -(g_scal[0] + g_scal[1]) / (2.f * (float)B);
        float embl = (sqrtf(g_scal[2]) + sqrtf(g_scal[3])) / (float)ni;
        out[0] = rec + 0.5f * aux + 1e-4f * embl;
    }
}

// ---------------------------------------------------------------------------
// Host orchestration (graph-capturable, fork/join dual stream)
// ---------------------------------------------------------------------------
#define TB 256
static inline int nblk(long long n) { return (int)((n + TB - 1) / TB); }

extern "C" void kernel_launch(void* const* d_in, const int* in_sizes, int n_in,
                              void* d_out, int out_size) {
    static cudaStream_t s1 = 0;
    static cudaEvent_t e0 = 0, e1 = 0, e2 = 0, e3 = 0, e4 = 0, e5 = 0;
    if (!s1) {
        cudaStreamCreateWithFlags(&s1, cudaStreamNonBlocking);
        cudaEventCreateWithFlags(&e0, cudaEventDisableTiming);
        cudaEventCreateWithFlags(&e1, cudaEventDisableTiming);
        cudaEventCreateWithFlags(&e2, cudaEventDisableTiming);
        cudaEventCreateWithFlags(&e3, cudaEventDisableTiming);
        cudaEventCreateWithFlags(&e4, cudaEventDisableTiming);
        cudaEventCreateWithFlags(&e5, cudaEventDisableTiming);
    }

    const float* user  = (const float*)d_in[0];
    const float* item  = (const float*)d_in[1];
    const int*   batch = (const int*)  d_in[2];
    const int2*  aux   = (const int2*) d_in[3];
    const int2*  tgt   = (const int2*) d_in[4];

    const int nu   = in_sizes[0] / D;
    const int ni   = in_sizes[1] / D;
    const int ntot = nu + ni;
    const int B    = in_sizes[2] / 9;
    const int Ea   = in_sizes[3] / 4;
    const int Et   = in_sizes[4] / 2;

    float *emb, *pc0, *pc1, *ae0, *ae1, *a0, *a1, *dnv;
    float2* dnv2;
    int *degi, *off, *curs, *csr;
    void* p;
    cudaGetSymbolAddress(&p, g_emb);  emb = (float*)p;
    cudaGetSymbolAddress(&p, g_pc0);  pc0 = (float*)p;
    cudaGetSymbolAddress(&p, g_pc1);  pc1 = (float*)p;
    cudaGetSymbolAddress(&p, g_ae0);  ae0 = (float*)p;
    cudaGetSymbolAddress(&p, g_ae1);  ae1 = (float*)p;
    cudaGetSymbolAddress(&p, g_a0);   a0  = (float*)p;
    cudaGetSymbolAddress(&p, g_a1);   a1  = (float*)p;
    cudaGetSymbolAddress(&p, g_dnv);  dnv = (float*)p;
    cudaGetSymbolAddress(&p, g_dnv2); dnv2 = (float2*)p;
    cudaGetSymbolAddress(&p, g_degi); degi = (int*)p;
    cudaGetSymbolAddress(&p, g_off);  off  = (int*)p;
    cudaGetSymbolAddress(&p, g_curs); curs = (int*)p;
    cudaGetSymbolAddress(&p, g_csr);  csr  = (int*)p;
    void* scalp; cudaGetSymbolAddress(&scalp, g_scal);

    const float* wC0 = dnv + 0 * NTOT_C;
    const float* wC1 = dnv + 1 * NTOT_C;
    const float* wA0 = dnv + 2 * NTOT_C;
    const float* wA1 = dnv + 3 * NTOT_C;
    const float* wT  = dnv + 4 * NTOT_C;

    // ---- init + fork sumsq to side stream ----
    cudaMemsetAsync(scalp, 0, 4 * sizeof(float), 0);
    cudaEventRecord(e0, 0);
    cudaStreamWaitEvent(s1, e0, 0);
    {
        dim3 g(512, 2);
        k_sumsq2<<<g, TB, 0, s1>>>(user, nu * D, item, ni * D);
    }
    cudaMemcpyAsync(emb, user, (size_t)nu * D * sizeof(float), cudaMemcpyDeviceToDevice, 0);
    cudaMemcpyAsync(emb + (size_t)nu * D, item, (size_t)ni * D * sizeof(float),
                    cudaMemcpyDeviceToDevice, 0);

    // ---- build ----
    cudaMemsetAsync(degi, 0, 3 * NTOT_C * sizeof(int), 0);
    k_deg3<<<nblk(2LL * Ea + Et), TB>>>(aux, tgt, Ea, Et, nu);
    k_dinv5<<<nblk(NTOT_C), TB>>>();
    dim3 gScan(NBLK_SCAN, 3);
    k_scanA<<<gScan, SCAN_B>>>();
    k_scanB<<<3, 1024>>>(NBLK_SCAN);
    k_scanC<<<gScan, SCAN_B>>>();
    cudaMemcpyAsync(curs, off, 3 * NOFF * sizeof(int), cudaMemcpyDeviceToDevice, 0);

    const long long bA0 = 0, bA1 = 2LL * Ea, bT = 4LL * Ea;
    const int* offA0 = off + 0 * NOFF;
    const int* offA1 = off + 1 * NOFF;
    const int* offT  = off + 2 * NOFF;
    const int nquad = (ntot + 3) / 4;
    const int gcnB4 = nblk((long long)nquad * 32);
    const int sblk  = nblk((long long)B * 32);
    const int sblk4 = nblk((long long)((B + 3) / 4) * 32);

    // fork tgt fill to side stream; aux fill + aux layer-1 on main
    cudaEventRecord(e4, 0);
    cudaStreamWaitEvent(s1, e4, 0);
    k_fill_tgt<<<nblk(Et), TB, 0, s1>>>(tgt, Et, bT, nu);
    cudaEventRecord(e5, s1);

    k_fill_aux<<<nblk(2LL * Ea), TB>>>(aux, Ea, nu);

    // ---- layer-1 (quad-node dual-weight) ----
    k_dual_w4<<<gcnB4, TB>>>(csr + bA0, offA0, emb, dnv2 + 0 * NTOT_C, wC0, wA0,
                             pc0, a0, ntot, 0);
    k_dual_w4<<<gcnB4, TB>>>(csr + bA1, offA1, emb, dnv2 + 1 * NTOT_C, wC1, wA1,
                             pc1, a1, ntot, 0);
    cudaStreamWaitEvent(0, e5, 0);   // tgt CSR ready
    k_dual_w4<<<gcnB4, TB>>>(csr + bT,  offT,  emb, dnv2 + 2 * NTOT_C, wC0, wC1,
                             pc0, pc1, ntot, 1);

    // fork comb scoring to side stream
    cudaEventRecord(e1, 0);
    cudaStreamWaitEvent(s1, e1, 0);
    {
        dim3 g(sblk, 2);
        k_score_comb<<<g, TB, 0, s1>>>(csr + bA0, offA0, csr + bA1, offA1,
                                       csr + bT, offT, wC0, wC1, pc0, pc1, emb,
                                       batch, B, nu);
    }

    // ---- aux layer-2 -> ae (quad nodes) ----
    k_gcn_w4<<<gcnB4, TB>>>(csr + bA0, offA0, wA0, a0, emb, ae0, ntot);
    k_gcn_w4<<<gcnB4, TB>>>(csr + bA1, offA1, wA1, a1, emb, ae1, ntot);

    // fork aux scores to side stream
    cudaEventRecord(e2, 0);
    cudaStreamWaitEvent(s1, e2, 0);
    k_scores_aux2<<<sblk, TB, 0, s1>>>(ae0, ae1, batch, B, nu);

    // ---- de layer-1 (quad nodes, dual source) + quad-packed de scoring ----
    float* d0 = a0;
    float* d1 = a1;
    k_dual_s4<<<gcnB4, TB>>>(csr + bT, offT, ae0, ae1, wT, d0, d1, ntot);
    k_score_de4<<<sblk4, TB>>>(csr + bT, offT, wT, d0, d1, ae0, ae1, batch, B, nu);

    // ---- join + finalize ----
    cudaEventRecord(e3, s1);
    cudaStreamWaitEvent(0, e3, 0);
    k_final<<<1, TB>>>(B, ni, (float*)d_out);
}